// round 3
// baseline (speedup 1.0000x reference)
#include <cuda_runtime.h>
#include <math.h>

// Problem constants (shapes are fixed by the dataset)
#define NMAX 50000
#define EMAX 800000
#define GNUM 64
// F=64, HG=HL=128, feat width = 64 + 12*64 = 832

// ---------------- scratch (__device__ globals; no allocation allowed) ----------
__device__ float    d_pq[NMAX * 128];          // [p | q] per node
__device__ float    d_sum[NMAX * 64];
__device__ float    d_sumsq[NMAX * 64];
__device__ unsigned d_mnE[NMAX * 64];
__device__ unsigned d_mxE[NMAX * 64];
__device__ float    d_cnt[NMAX];
__device__ float    d_feat[(size_t)NMAX * 832];
__device__ float    d_h[NMAX * 128];
__device__ float    d_Wds[64 * 128];           // [Wd | Ws]
__device__ float    d_Wc[832 * 128];           // W_post @ W_lin
__device__ float    d_bc[128];                 // b_post @ W_lin + b_lin
__device__ float    d_v[64];                   // W_edge @ W_pre_e
__device__ float    d_cvec[64];                // b_edge @ W_pre_e + b_pre
__device__ float    d_zsum[GNUM * 128];
__device__ float    d_gcnt[GNUM];
__device__ float    d_gT[GNUM * 128];          // MLP temp
__device__ float    d_gR[GNUM * 128];          // MLP residual

// ------------- monotone float <-> uint encoding for atomic min/max -------------
__device__ __forceinline__ unsigned fenc(float f) {
    unsigned u = __float_as_uint(f);
    return (u & 0x80000000u) ? ~u : (u | 0x80000000u);
}
__device__ __forceinline__ float fdec(unsigned e) {
    unsigned u = (e & 0x80000000u) ? (e & 0x7FFFFFFFu) : ~e;
    return __uint_as_float(u);
}

// ------------------------------- init ------------------------------------------
__global__ void init_kernel(int Nn) {
    int i = blockIdx.x * blockDim.x + threadIdx.x;
    int tot = Nn * 64;
    if (i < tot) {
        d_sum[i]   = 0.f;
        d_sumsq[i] = 0.f;
        d_mnE[i]   = 0xFFFFFFFFu;   // +inf encoding
        d_mxE[i]   = 0u;            // -inf encoding
    }
    if (i < Nn)         d_cnt[i]  = 0.f;
    if (i < GNUM * 128) d_zsum[i] = 0.f;
    if (i < GNUM)       d_gcnt[i] = 0.f;
}

// --------------------------- tiny precomputes ----------------------------------
__global__ void prep_kernel(const float* __restrict__ W_edge, const float* __restrict__ b_edge,
                            const float* __restrict__ W_pre,  const float* __restrict__ b_pre,
                            const float* __restrict__ b_post, const float* __restrict__ W_lin,
                            const float* __restrict__ b_lin) {
    int i = blockIdx.x * blockDim.x + threadIdx.x;
    if (i < 64 * 128) {
        int k = i >> 7, j = i & 127;
        d_Wds[i] = (j < 64) ? W_pre[k * 64 + j] : W_pre[(64 + k) * 64 + (j - 64)];
    } else if (i < 64 * 128 + 128) {
        int j = i - 64 * 128;
        float acc = b_lin[j];
        for (int k = 0; k < 128; k++) acc = fmaf(b_post[k], W_lin[k * 128 + j], acc);
        d_bc[j] = acc;
    } else if (i < 64 * 128 + 128 + 64) {
        int j = i - (64 * 128 + 128);
        float av = 0.f, ac = 0.f;
        for (int k = 0; k < 64; k++) {
            float w = W_pre[(128 + k) * 64 + j];
            av = fmaf(W_edge[k], w, av);
            ac = fmaf(b_edge[k], w, ac);
        }
        d_v[j]    = av;
        d_cvec[j] = ac + b_pre[j];
    }
}

// ----------------------- generic 128x128x8 fp32 GEMM ---------------------------
// C[M,N] = A[M,K] @ B[K,N] (+ bias). Requires K % 8 == 0 and N covered by grid.x*128.
__global__ __launch_bounds__(256) void gemm128_kernel(
    const float* __restrict__ A, const float* __restrict__ B,
    const float* __restrict__ bias, float* __restrict__ C,
    int M, int K, int N) {
    __shared__ float As[8][132];
    __shared__ float Bs[8][132];
    const int tid  = threadIdx.x;
    const int row0 = blockIdx.y * 128;
    const int col0 = blockIdx.x * 128;
    const int tr   = (tid >> 4) << 3;   // 0..120
    const int tc   = (tid & 15) << 3;   // 0..120

    float acc[8][8];
#pragma unroll
    for (int i = 0; i < 8; i++)
#pragma unroll
        for (int j = 0; j < 8; j++) acc[i][j] = 0.f;

    for (int k0 = 0; k0 < K; k0 += 8) {
#pragma unroll
        for (int t = 0; t < 4; t++) {
            int id = tid + t * 256;
            int r = id >> 3, cc = id & 7;
            int gr = row0 + r;
            As[cc][r] = (gr < M) ? A[(size_t)gr * K + k0 + cc] : 0.f;
        }
#pragma unroll
        for (int t = 0; t < 4; t++) {
            int id = tid + t * 256;
            int r = id >> 7, cc = id & 127;
            int gc = col0 + cc;
            Bs[r][cc] = (gc < N) ? B[(size_t)(k0 + r) * N + gc] : 0.f;
        }
        __syncthreads();
#pragma unroll
        for (int kk = 0; kk < 8; kk++) {
            float4 a0 = *reinterpret_cast<const float4*>(&As[kk][tr]);
            float4 a1 = *reinterpret_cast<const float4*>(&As[kk][tr + 4]);
            float4 b0 = *reinterpret_cast<const float4*>(&Bs[kk][tc]);
            float4 b1 = *reinterpret_cast<const float4*>(&Bs[kk][tc + 4]);
            float a[8] = {a0.x, a0.y, a0.z, a0.w, a1.x, a1.y, a1.z, a1.w};
            float b[8] = {b0.x, b0.y, b0.z, b0.w, b1.x, b1.y, b1.z, b1.w};
#pragma unroll
            for (int i = 0; i < 8; i++)
#pragma unroll
                for (int j = 0; j < 8; j++) acc[i][j] = fmaf(a[i], b[j], acc[i][j]);
        }
        __syncthreads();
    }
#pragma unroll
    for (int i = 0; i < 8; i++) {
        int gr = row0 + tr + i;
        if (gr >= M) continue;
#pragma unroll
        for (int j = 0; j < 8; j++) {
            int gc = col0 + tc + j;
            if (gc >= N) continue;
            float v = acc[i][j];
            if (bias) v += bias[gc];
            C[(size_t)gr * N + gc] = v;
        }
    }
}

// ------------------------------- edge scatter ----------------------------------
// m[e,f] = p[dst,f] + q[src,f] + ea[e]*v[f] + c[f]; scatter to sum/sumsq/min/max/cnt at dst
__global__ void edge_kernel(const int* __restrict__ ei, const float* __restrict__ ea, int E) {
    int idx = blockIdx.x * blockDim.x + threadIdx.x;
    int e = idx >> 6;
    if (e >= E) return;
    int f = idx & 63;
    int s = ei[e];       // edge_index[0] = src
    int d = ei[E + e];   // edge_index[1] = dst
    float m = d_pq[d * 128 + f] + d_pq[s * 128 + 64 + f] + ea[e] * d_v[f] + d_cvec[f];
    int o = d * 64 + f;
    atomicAdd(&d_sum[o], m);
    atomicAdd(&d_sumsq[o], m * m);
    unsigned enc = fenc(m);
    atomicMin(&d_mnE[o], enc);
    atomicMax(&d_mxE[o], enc);
    if (f == 0) atomicAdd(&d_cnt[d], 1.f);
}

// ------------------------- per-node 832-wide feature ---------------------------
__global__ void feat_kernel(const float* __restrict__ x, int Nn) {
    int idx = blockIdx.x * blockDim.x + threadIdx.x;
    int n = idx >> 6;
    if (n >= Nn) return;
    int f = idx & 63;
    float ct   = d_cnt[n];
    float cnt1 = fmaxf(ct, 1.f);
    float inv  = 1.f / cnt1;
    int o = n * 64 + f;
    float mean  = d_sum[o] * inv;
    float mean2 = d_sumsq[o] * inv;
    float var   = mean2 - mean * mean;
    float sd    = sqrtf(fmaxf(var, 0.f) + 1e-5f);
    bool  has   = ct > 0.f;
    float vmn   = has ? fdec(d_mnE[o]) : 0.f;
    float vmx   = has ? fdec(d_mxE[o]) : 0.f;
    float amp   = logf(cnt1 + 1.f) * (1.0f / 2.19722457733621938f);  // / log(9)
    float iamp  = 1.f / amp;
    float* Fp = d_feat + (size_t)n * 832;
    Fp[f]        = x[n * 64 + f];
    Fp[64 + f]   = mean;        Fp[128 + f] = vmn;        Fp[192 + f] = vmx;        Fp[256 + f] = sd;
    Fp[320 + f]  = mean * amp;  Fp[384 + f] = vmn * amp;  Fp[448 + f] = vmx * amp;  Fp[512 + f] = sd * amp;
    Fp[576 + f]  = mean * iamp; Fp[640 + f] = vmn * iamp; Fp[704 + f] = vmx * iamp; Fp[768 + f] = sd * iamp;
}

// --------------------------------- pooling -------------------------------------
__global__ void pool_kernel(const int* __restrict__ batch, int Nn) {
    int idx = blockIdx.x * blockDim.x + threadIdx.x;
    int n = idx >> 7;
    if (n >= Nn) return;
    int j = idx & 127;
    int g = batch[n];
    atomicAdd(&d_zsum[g * 128 + j], d_h[n * 128 + j]);
    if (j == 0) atomicAdd(&d_gcnt[g], 1.f);
}

// ------------------------------- MLP head --------------------------------------
// Single block, 128 threads; thread j owns column j. BN is per-column -> no
// cross-thread reduction needed.
__device__ __forceinline__ void mlp_layer(float* zS, const float* __restrict__ W,
                                          const float* __restrict__ b,
                                          const float* __restrict__ g,
                                          const float* __restrict__ be, int j,
                                          float* rsave, const float* radd) {
    // gT = zS @ W + b   (reads all columns of zS -> zS must be stable on entry)
    for (int i = 0; i < 64; i++) {
        float acc = b[j];
        for (int k = 0; k < 128; k++) acc = fmaf(zS[i * 128 + k], W[k * 128 + j], acc);
        d_gT[i * 128 + j] = acc;
    }
    // BN stats over this thread's own column
    float mu = 0.f;
    for (int i = 0; i < 64; i++) mu += d_gT[i * 128 + j];
    mu *= (1.f / 64.f);
    float var = 0.f;
    for (int i = 0; i < 64; i++) { float t = d_gT[i * 128 + j] - mu; var = fmaf(t, t, var); }
    var *= (1.f / 64.f);
    float is = rsqrtf(var + 1e-5f);
    float sg = g[j] * is;
    float sb = be[j] - mu * sg;
    __syncthreads();   // everyone done READING zS
    for (int i = 0; i < 64; i++) {
        float val = d_gT[i * 128 + j] * sg + sb;
        if (radd) val += radd[i * 128 + j];
        val = fmaxf(val, 0.f);
        zS[i * 128 + j] = val;
        if (rsave) rsave[i * 128 + j] = val;
    }
    __syncthreads();
}

__global__ void mlp_kernel(const float* __restrict__ g1,  const float* __restrict__ be1,
                           const float* __restrict__ W2,  const float* __restrict__ b2,
                           const float* __restrict__ g2,  const float* __restrict__ be2,
                           const float* __restrict__ Wr1, const float* __restrict__ br1,
                           const float* __restrict__ gr1, const float* __restrict__ ber1,
                           const float* __restrict__ Wr2, const float* __restrict__ br2,
                           const float* __restrict__ gr2, const float* __restrict__ ber2,
                           const float* __restrict__ Wout, const float* __restrict__ bout,
                           float* __restrict__ out) {
    __shared__ float zS[64 * 128];
    const int j = threadIdx.x;
    // pooled mean + bn1 + relu (column-local, no sync needed yet)
    for (int i = 0; i < 64; i++) {
        float gc = fmaxf(d_gcnt[i], 1.f);
        zS[i * 128 + j] = d_zsum[i * 128 + j] / gc;
    }
    {
        float mu = 0.f;
        for (int i = 0; i < 64; i++) mu += zS[i * 128 + j];
        mu *= (1.f / 64.f);
        float var = 0.f;
        for (int i = 0; i < 64; i++) { float t = zS[i * 128 + j] - mu; var = fmaf(t, t, var); }
        var *= (1.f / 64.f);
        float is = rsqrtf(var + 1e-5f);
        float sg = g1[j] * is;
        float sb = be1[j] - mu * sg;
        for (int i = 0; i < 64; i++) zS[i * 128 + j] = fmaxf(zS[i * 128 + j] * sg + sb, 0.f);
    }
    __syncthreads();

    mlp_layer(zS, W2,  b2,  g2,  be2,  j, d_gR,   nullptr);  // save residual
    mlp_layer(zS, Wr1, br1, gr1, ber1, j, nullptr, nullptr);
    mlp_layer(zS, Wr2, br2, gr2, ber2, j, nullptr, d_gR);    // add residual

    if (j < 64) {
        float acc = bout[0];
        for (int k = 0; k < 128; k++) acc = fmaf(zS[j * 128 + k], Wout[k], acc);
        out[j] = acc;
    }
}

// --------------------------------- launch --------------------------------------
extern "C" void kernel_launch(void* const* d_in, const int* in_sizes, int n_in,
                              void* d_out, int out_size) {
    const float* x      = (const float*)d_in[0];
    const int*   ei     = (const int*)d_in[1];
    const float* ea     = (const float*)d_in[2];
    const int*   batch  = (const int*)d_in[3];
    const float* W_edge = (const float*)d_in[4];
    const float* b_edge = (const float*)d_in[5];
    const float* W_pre  = (const float*)d_in[6];
    const float* b_pre  = (const float*)d_in[7];
    const float* W_post = (const float*)d_in[8];
    const float* b_post = (const float*)d_in[9];
    const float* W_lin  = (const float*)d_in[10];
    const float* b_lin  = (const float*)d_in[11];
    const float* g1  = (const float*)d_in[12];
    const float* be1 = (const float*)d_in[13];
    const float* W2  = (const float*)d_in[14];
    const float* b2  = (const float*)d_in[15];
    const float* g2  = (const float*)d_in[16];
    const float* be2 = (const float*)d_in[17];
    const float* Wr1 = (const float*)d_in[18];
    const float* br1 = (const float*)d_in[19];
    const float* gr1 = (const float*)d_in[20];
    const float* ber1= (const float*)d_in[21];
    const float* Wr2 = (const float*)d_in[22];
    const float* br2 = (const float*)d_in[23];
    const float* gr2 = (const float*)d_in[24];
    const float* ber2= (const float*)d_in[25];
    const float* Wout= (const float*)d_in[26];
    const float* bout= (const float*)d_in[27];
    float* out = (float*)d_out;

    const int Nn = in_sizes[0] / 64;
    const int E  = in_sizes[2];

    void *p_pq, *p_Wds, *p_Wc, *p_bc, *p_feat, *p_h;
    cudaGetSymbolAddress(&p_pq,   d_pq);
    cudaGetSymbolAddress(&p_Wds,  d_Wds);
    cudaGetSymbolAddress(&p_Wc,   d_Wc);
    cudaGetSymbolAddress(&p_bc,   d_bc);
    cudaGetSymbolAddress(&p_feat, d_feat);
    cudaGetSymbolAddress(&p_h,    d_h);

    init_kernel<<<(Nn * 64 + 255) / 256, 256>>>(Nn);
    prep_kernel<<<(64 * 128 + 128 + 64 + 255) / 256, 256>>>(W_edge, b_edge, W_pre, b_pre,
                                                            b_post, W_lin, b_lin);
    {   // Wc = W_post @ W_lin   [832,128] @ [128,128]
        dim3 g(1, (832 + 127) / 128);
        gemm128_kernel<<<g, 256>>>(W_post, W_lin, nullptr, (float*)p_Wc, 832, 128, 128);
    }
    {   // pq = x @ [Wd|Ws]      [N,64] @ [64,128]
        dim3 g(1, (Nn + 127) / 128);
        gemm128_kernel<<<g, 256>>>(x, (const float*)p_Wds, nullptr, (float*)p_pq, Nn, 64, 128);
    }
    edge_kernel<<<(int)(((long long)E * 64 + 255) / 256), 256>>>(ei, ea, E);
    feat_kernel<<<(Nn * 64 + 255) / 256, 256>>>(x, Nn);
    {   // h = feat @ Wc + bc    [N,832] @ [832,128]
        dim3 g(1, (Nn + 127) / 128);
        gemm128_kernel<<<g, 256>>>((const float*)p_feat, (const float*)p_Wc,
                                   (const float*)p_bc, (float*)p_h, Nn, 832, 128);
    }
    pool_kernel<<<(Nn * 128 + 255) / 256, 256>>>(batch, Nn);
    mlp_kernel<<<1, 128>>>(g1, be1, W2, b2, g2, be2, Wr1, br1, gr1, ber1,
                           Wr2, br2, gr2, ber2, Wout, bout, out);
}

// round 4
// speedup vs baseline: 1.4262x; 1.4262x over previous
#include <cuda_runtime.h>
#include <math.h>

// Problem constants (shapes fixed by dataset)
#define NMAX 50000
#define EMAX 800000
#define GNUM 64
// F=64, HG=HL=128, feat width = 64 + 12*64 = 832

// ---------------- scratch (__device__ globals; no allocation allowed) ----------
__device__ float    d_pq[NMAX * 128];          // [p | q] per node
__device__ int      d_deg[NMAX];
__device__ int      d_off[NMAX];
__device__ int      d_fill[NMAX];
__device__ int      d_srcS[EMAX];              // src reordered by dst-CSR position
__device__ float    d_eaS[EMAX];               // edge_attr reordered likewise
__device__ float    d_feat[(size_t)NMAX * 832];
__device__ float    d_h[NMAX * 128];
__device__ float    d_Wds[64 * 128];           // [Wd | Ws]
__device__ float    d_Wc[832 * 128];           // W_post @ W_lin
__device__ float    d_bc[128];                 // b_post @ W_lin + b_lin
__device__ float    d_v[64];                   // W_edge @ W_pre_e
__device__ float    d_cvec[64];                // b_edge @ W_pre_e + b_pre
__device__ float    d_zsum[GNUM * 128];
__device__ float    d_gcnt[GNUM];

// ------------------------------- init ------------------------------------------
__global__ void init_kernel(int Nn) {
    int i = blockIdx.x * blockDim.x + threadIdx.x;
    if (i < Nn)         d_deg[i]  = 0;
    if (i < GNUM * 128) d_zsum[i] = 0.f;
    if (i < GNUM)       d_gcnt[i] = 0.f;
}

// --------------------------- tiny precomputes ----------------------------------
__global__ void prep_kernel(const float* __restrict__ W_edge, const float* __restrict__ b_edge,
                            const float* __restrict__ W_pre,  const float* __restrict__ b_pre,
                            const float* __restrict__ b_post, const float* __restrict__ W_lin,
                            const float* __restrict__ b_lin) {
    int i = blockIdx.x * blockDim.x + threadIdx.x;
    if (i < 64 * 128) {
        int k = i >> 7, j = i & 127;
        d_Wds[i] = (j < 64) ? W_pre[k * 64 + j] : W_pre[(64 + k) * 64 + (j - 64)];
    } else if (i < 64 * 128 + 128) {
        int j = i - 64 * 128;
        float acc = b_lin[j];
        for (int k = 0; k < 128; k++) acc = fmaf(b_post[k], W_lin[k * 128 + j], acc);
        d_bc[j] = acc;
    } else if (i < 64 * 128 + 128 + 64) {
        int j = i - (64 * 128 + 128);
        float av = 0.f, ac = 0.f;
        for (int k = 0; k < 64; k++) {
            float w = W_pre[(128 + k) * 64 + j];
            av = fmaf(W_edge[k], w, av);
            ac = fmaf(b_edge[k], w, ac);
        }
        d_v[j]    = av;
        d_cvec[j] = ac + b_pre[j];
    }
}

// ----------------------- generic 128x128x8 fp32 GEMM ---------------------------
__global__ __launch_bounds__(256) void gemm128_kernel(
    const float* __restrict__ A, const float* __restrict__ B,
    const float* __restrict__ bias, float* __restrict__ C,
    int M, int K, int N) {
    __shared__ float As[8][132];
    __shared__ float Bs[8][132];
    const int tid  = threadIdx.x;
    const int row0 = blockIdx.y * 128;
    const int col0 = blockIdx.x * 128;
    const int tr   = (tid >> 4) << 3;
    const int tc   = (tid & 15) << 3;

    float acc[8][8];
#pragma unroll
    for (int i = 0; i < 8; i++)
#pragma unroll
        for (int j = 0; j < 8; j++) acc[i][j] = 0.f;

    for (int k0 = 0; k0 < K; k0 += 8) {
#pragma unroll
        for (int t = 0; t < 4; t++) {
            int id = tid + t * 256;
            int r = id >> 3, cc = id & 7;
            int gr = row0 + r;
            As[cc][r] = (gr < M) ? A[(size_t)gr * K + k0 + cc] : 0.f;
        }
#pragma unroll
        for (int t = 0; t < 4; t++) {
            int id = tid + t * 256;
            int r = id >> 7, cc = id & 127;
            int gc = col0 + cc;
            Bs[r][cc] = (gc < N) ? B[(size_t)(k0 + r) * N + gc] : 0.f;
        }
        __syncthreads();
#pragma unroll
        for (int kk = 0; kk < 8; kk++) {
            float4 a0 = *reinterpret_cast<const float4*>(&As[kk][tr]);
            float4 a1 = *reinterpret_cast<const float4*>(&As[kk][tr + 4]);
            float4 b0 = *reinterpret_cast<const float4*>(&Bs[kk][tc]);
            float4 b1 = *reinterpret_cast<const float4*>(&Bs[kk][tc + 4]);
            float a[8] = {a0.x, a0.y, a0.z, a0.w, a1.x, a1.y, a1.z, a1.w};
            float b[8] = {b0.x, b0.y, b0.z, b0.w, b1.x, b1.y, b1.z, b1.w};
#pragma unroll
            for (int i = 0; i < 8; i++)
#pragma unroll
                for (int j = 0; j < 8; j++) acc[i][j] = fmaf(a[i], b[j], acc[i][j]);
        }
        __syncthreads();
    }
#pragma unroll
    for (int i = 0; i < 8; i++) {
        int gr = row0 + tr + i;
        if (gr >= M) continue;
#pragma unroll
        for (int j = 0; j < 8; j++) {
            int gc = col0 + tc + j;
            if (gc >= N) continue;
            float v = acc[i][j];
            if (bias) v += bias[gc];
            C[(size_t)gr * N + gc] = v;
        }
    }
}

// ------------------------------- CSR build -------------------------------------
__global__ void count_kernel(const int* __restrict__ ei, int E) {
    int e = blockIdx.x * blockDim.x + threadIdx.x;
    if (e >= E) return;
    atomicAdd(&d_deg[ei[E + e]], 1);
}

__global__ void scan_kernel(int Nn) {
    __shared__ int sh[1024];
    int t = threadIdx.x;
    int C = (Nn + 1023) >> 10;
    int start = t * C;
    int end = start + C; if (end > Nn) end = Nn;
    int local = 0;
    for (int i = start; i < end; i++) local += d_deg[i];
    sh[t] = local;
    __syncthreads();
    for (int d = 1; d < 1024; d <<= 1) {
        int v = (t >= d) ? sh[t - d] : 0;
        __syncthreads();
        sh[t] += v;
        __syncthreads();
    }
    int run = (t == 0) ? 0 : sh[t - 1];
    for (int i = start; i < end; i++) {
        d_off[i] = run;
        d_fill[i] = run;
        run += d_deg[i];
    }
}

__global__ void scatter_kernel(const int* __restrict__ ei, const float* __restrict__ ea, int E) {
    int e = blockIdx.x * blockDim.x + threadIdx.x;
    if (e >= E) return;
    int d = ei[E + e];
    int pos = atomicAdd(&d_fill[d], 1);
    d_srcS[pos] = ei[e];
    d_eaS[pos]  = ea[e];
}

// -------- per-node aggregation (no atomics) + 832-wide feature write -----------
// 256 threads = 4 nodes x 64 feature-threads.
__global__ __launch_bounds__(256) void agg_kernel(const float* __restrict__ x, int Nn) {
    int tid = threadIdx.x;
    int n = blockIdx.x * 4 + (tid >> 6);
    if (n >= Nn) return;
    int f = tid & 63;

    int off = d_off[n];
    int deg = d_deg[n];
    float pdf = d_pq[n * 128 + f];
    float vf  = d_v[f];
    float cf  = d_cvec[f];

    float sum = 0.f, sq = 0.f;
    float mn = INFINITY, mx = -INFINITY;
#pragma unroll 2
    for (int jj = 0; jj < deg; jj++) {
        int   s   = d_srcS[off + jj];
        float eav = d_eaS[off + jj];
        float m = pdf + d_pq[s * 128 + 64 + f] + eav * vf + cf;
        sum += m;
        sq = fmaf(m, m, sq);
        mn = fminf(mn, m);
        mx = fmaxf(mx, m);
    }

    float ct    = (float)deg;
    float cnt1  = fmaxf(ct, 1.f);
    float inv   = 1.f / cnt1;
    float mean  = sum * inv;
    float mean2 = sq * inv;
    float var   = mean2 - mean * mean;
    float sd    = sqrtf(fmaxf(var, 0.f) + 1e-5f);
    float vmn   = (deg > 0) ? mn : 0.f;
    float vmx   = (deg > 0) ? mx : 0.f;
    float amp   = logf(cnt1 + 1.f) * (1.0f / 2.19722457733621938f);  // / log(9)
    float iamp  = 1.f / amp;

    float* Fp = d_feat + (size_t)n * 832;
    Fp[f]        = x[n * 64 + f];
    Fp[64 + f]   = mean;        Fp[128 + f] = vmn;        Fp[192 + f] = vmx;        Fp[256 + f] = sd;
    Fp[320 + f]  = mean * amp;  Fp[384 + f] = vmn * amp;  Fp[448 + f] = vmx * amp;  Fp[512 + f] = sd * amp;
    Fp[576 + f]  = mean * iamp; Fp[640 + f] = vmn * iamp; Fp[704 + f] = vmx * iamp; Fp[768 + f] = sd * iamp;
}

// --------------------------------- pooling -------------------------------------
__global__ void pool_kernel(const int* __restrict__ batch, int Nn) {
    int idx = blockIdx.x * blockDim.x + threadIdx.x;
    int n = idx >> 7;
    if (n >= Nn) return;
    int j = idx & 127;
    int g = batch[n];
    atomicAdd(&d_zsum[g * 128 + j], d_h[n * 128 + j]);
    if (j == 0) atomicAdd(&d_gcnt[g], 1.f);
}

// ------------------------------- MLP head --------------------------------------
// 1024 threads: rr = tid>>7 (row group, 8 rows strided by 8), j = tid&127 (column).
__device__ __forceinline__ void mlp_stats(float ps, float pq2, int rr, int j,
                                          float* redS, float* redQ,
                                          float* sgS, float* sbS,
                                          const float* __restrict__ g,
                                          const float* __restrict__ be) {
    redS[rr * 128 + j] = ps;
    redQ[rr * 128 + j] = pq2;
    __syncthreads();
    if (rr == 0) {
        float s = 0.f, q = 0.f;
#pragma unroll
        for (int r = 0; r < 8; r++) { s += redS[r * 128 + j]; q += redQ[r * 128 + j]; }
        float mu  = s * (1.f / 64.f);
        float var = q * (1.f / 64.f) - mu * mu;
        float is  = rsqrtf(fmaxf(var, 0.f) + 1e-5f);
        float sg  = g[j] * is;
        sgS[j] = sg;
        sbS[j] = be[j] - mu * sg;
    }
    __syncthreads();
}

__device__ __forceinline__ void mlp_layer(float* zS, float* redS, float* redQ,
                                          float* sgS, float* sbS,
                                          const float* __restrict__ W, const float* __restrict__ b,
                                          const float* __restrict__ g, const float* __restrict__ be,
                                          int rr, int j, float* rsave, const float* radd) {
    float acc[8];
#pragma unroll
    for (int u = 0; u < 8; u++) {
        int i = rr + u * 8;
        float a = b[j];
        for (int k = 0; k < 128; k++) a = fmaf(zS[i * 128 + k], W[k * 128 + j], a);
        acc[u] = a;
    }
    float ps = 0.f, pq2 = 0.f;
#pragma unroll
    for (int u = 0; u < 8; u++) { ps += acc[u]; pq2 = fmaf(acc[u], acc[u], pq2); }
    mlp_stats(ps, pq2, rr, j, redS, redQ, sgS, sbS, g, be);   // syncs cover zS reads
#pragma unroll
    for (int u = 0; u < 8; u++) {
        float val = acc[u] * sgS[j] + sbS[j];
        if (radd) val += radd[u];
        val = fmaxf(val, 0.f);
        zS[(rr + u * 8) * 128 + j] = val;
        if (rsave) rsave[u] = val;
    }
    __syncthreads();
}

__global__ __launch_bounds__(1024) void mlp_kernel(
        const float* __restrict__ g1,  const float* __restrict__ be1,
        const float* __restrict__ W2,  const float* __restrict__ b2,
        const float* __restrict__ g2,  const float* __restrict__ be2,
        const float* __restrict__ Wr1, const float* __restrict__ br1,
        const float* __restrict__ gr1, const float* __restrict__ ber1,
        const float* __restrict__ Wr2, const float* __restrict__ br2,
        const float* __restrict__ gr2, const float* __restrict__ ber2,
        const float* __restrict__ Wout, const float* __restrict__ bout,
        float* __restrict__ out) {
    __shared__ float zS[64 * 128];
    __shared__ float redS[8 * 128];
    __shared__ float redQ[8 * 128];
    __shared__ float sgS[128], sbS[128];
    int tid = threadIdx.x;
    int rr = tid >> 7, j = tid & 127;

    // pooled mean
    float v8[8];
#pragma unroll
    for (int u = 0; u < 8; u++) {
        int i = rr + u * 8;
        float gc = fmaxf(d_gcnt[i], 1.f);
        v8[u] = d_zsum[i * 128 + j] / gc;
    }
    // bn1 + relu
    {
        float ps = 0.f, pq2 = 0.f;
#pragma unroll
        for (int u = 0; u < 8; u++) { ps += v8[u]; pq2 = fmaf(v8[u], v8[u], pq2); }
        mlp_stats(ps, pq2, rr, j, redS, redQ, sgS, sbS, g1, be1);
#pragma unroll
        for (int u = 0; u < 8; u++)
            zS[(rr + u * 8) * 128 + j] = fmaxf(v8[u] * sgS[j] + sbS[j], 0.f);
        __syncthreads();
    }

    float res[8];
    mlp_layer(zS, redS, redQ, sgS, sbS, W2,  b2,  g2,  be2,  rr, j, res,    nullptr);
    mlp_layer(zS, redS, redQ, sgS, sbS, Wr1, br1, gr1, ber1, rr, j, nullptr, nullptr);
    mlp_layer(zS, redS, redQ, sgS, sbS, Wr2, br2, gr2, ber2, rr, j, nullptr, res);

    if (tid < 64) {
        float a = bout[0];
        for (int k = 0; k < 128; k++) a = fmaf(zS[tid * 128 + k], Wout[k], a);
        out[tid] = a;
    }
}

// --------------------------------- launch --------------------------------------
extern "C" void kernel_launch(void* const* d_in, const int* in_sizes, int n_in,
                              void* d_out, int out_size) {
    const float* x      = (const float*)d_in[0];
    const int*   ei     = (const int*)d_in[1];
    const float* ea     = (const float*)d_in[2];
    const int*   batch  = (const int*)d_in[3];
    const float* W_edge = (const float*)d_in[4];
    const float* b_edge = (const float*)d_in[5];
    const float* W_pre  = (const float*)d_in[6];
    const float* b_pre  = (const float*)d_in[7];
    const float* W_post = (const float*)d_in[8];
    const float* b_post = (const float*)d_in[9];
    const float* W_lin  = (const float*)d_in[10];
    const float* b_lin  = (const float*)d_in[11];
    const float* g1  = (const float*)d_in[12];
    const float* be1 = (const float*)d_in[13];
    const float* W2  = (const float*)d_in[14];
    const float* b2  = (const float*)d_in[15];
    const float* g2  = (const float*)d_in[16];
    const float* be2 = (const float*)d_in[17];
    const float* Wr1 = (const float*)d_in[18];
    const float* br1 = (const float*)d_in[19];
    const float* gr1 = (const float*)d_in[20];
    const float* ber1= (const float*)d_in[21];
    const float* Wr2 = (const float*)d_in[22];
    const float* br2 = (const float*)d_in[23];
    const float* gr2 = (const float*)d_in[24];
    const float* ber2= (const float*)d_in[25];
    const float* Wout= (const float*)d_in[26];
    const float* bout= (const float*)d_in[27];
    float* out = (float*)d_out;

    const int Nn = in_sizes[0] / 64;
    const int E  = in_sizes[2];

    void *p_pq, *p_Wds, *p_Wc, *p_bc, *p_feat, *p_h;
    cudaGetSymbolAddress(&p_pq,   d_pq);
    cudaGetSymbolAddress(&p_Wds,  d_Wds);
    cudaGetSymbolAddress(&p_Wc,   d_Wc);
    cudaGetSymbolAddress(&p_bc,   d_bc);
    cudaGetSymbolAddress(&p_feat, d_feat);
    cudaGetSymbolAddress(&p_h,    d_h);

    init_kernel<<<(Nn + 255) / 256, 256>>>(Nn);
    prep_kernel<<<(64 * 128 + 128 + 64 + 255) / 256, 256>>>(W_edge, b_edge, W_pre, b_pre,
                                                            b_post, W_lin, b_lin);
    {   // Wc = W_post @ W_lin   [832,128] @ [128,128]
        dim3 g(1, (832 + 127) / 128);
        gemm128_kernel<<<g, 256>>>(W_post, W_lin, nullptr, (float*)p_Wc, 832, 128, 128);
    }
    {   // pq = x @ [Wd|Ws]      [N,64] @ [64,128]
        dim3 g(1, (Nn + 127) / 128);
        gemm128_kernel<<<g, 256>>>(x, (const float*)p_Wds, nullptr, (float*)p_pq, Nn, 64, 128);
    }
    count_kernel<<<(E + 255) / 256, 256>>>(ei, E);
    scan_kernel<<<1, 1024>>>(Nn);
    scatter_kernel<<<(E + 255) / 256, 256>>>(ei, ea, E);
    agg_kernel<<<(Nn + 3) / 4, 256>>>(x, Nn);
    {   // h = feat @ Wc + bc    [N,832] @ [832,128]
        dim3 g(1, (Nn + 127) / 128);
        gemm128_kernel<<<g, 256>>>((const float*)p_feat, (const float*)p_Wc,
                                   (const float*)p_bc, (float*)p_h, Nn, 832, 128);
    }
    pool_kernel<<<(Nn * 128 + 255) / 256, 256>>>(batch, Nn);
    mlp_kernel<<<1, 1024>>>(g1, be1, W2, b2, g2, be2, Wr1, br1, gr1, ber1,
                            Wr2, br2, gr2, ber2, Wout, bout, out);
}

// round 6
// speedup vs baseline: 1.8319x; 1.2845x over previous
#include <cuda_runtime.h>
#include <math.h>

// Problem constants (shapes fixed by dataset)
#define NMAX 50000
#define EMAX 800000
#define GNUM 64
// F=64, HG=HL=128; virtual feat width = 64 + 12*64 = 832

// ---------------- scratch (__device__ globals; no allocation allowed) ----------
__device__ float    d_pq[NMAX * 128];          // [p | q] per node
__device__ int      d_deg[NMAX];
__device__ int      d_off[NMAX];
__device__ int      d_fill[NMAX];
__device__ int      d_srcS[EMAX];              // src reordered by dst-CSR position
__device__ float    d_eaS[EMAX];               // edge_attr reordered likewise
__device__ float    d_agg[(size_t)NMAX * 256]; // [mean|mn|mx|sd] per node
__device__ float    d_amp[NMAX];
__device__ float    d_iamp[NMAX];
__device__ float    d_h[NMAX * 128];
__device__ float    d_Wds[64 * 128];           // [Wd | Ws]
__device__ float    d_Wc[832 * 128];           // W_post @ W_lin
__device__ float    d_bc[128];                 // b_post @ W_lin + b_lin
__device__ float    d_v[64];                   // W_edge @ W_pre_e
__device__ float    d_cvec[64];                // b_edge @ W_pre_e + b_pre
__device__ float    d_zsum[GNUM * 128];
__device__ float    d_gcnt[GNUM];

// ------------------------- f32x2 packed helpers --------------------------------
__device__ __forceinline__ unsigned long long dup2(float x) {
    unsigned long long r;
    asm("mov.b64 %0, {%1, %1};" : "=l"(r) : "f"(x));
    return r;
}
__device__ __forceinline__ unsigned long long fma2(unsigned long long a,
                                                   unsigned long long b,
                                                   unsigned long long c) {
    unsigned long long d;
    asm("fma.rn.f32x2 %0, %1, %2, %3;" : "=l"(d) : "l"(a), "l"(b), "l"(c));
    return d;
}
__device__ __forceinline__ void unpack2(unsigned long long u, float& lo, float& hi) {
    asm("mov.b64 {%0, %1}, %2;" : "=f"(lo), "=f"(hi) : "l"(u));
}

// ------------------------------- init ------------------------------------------
__global__ void init_kernel(int Nn) {
    int i = blockIdx.x * blockDim.x + threadIdx.x;
    if (i < Nn)         d_deg[i]  = 0;
    if (i < GNUM * 128) d_zsum[i] = 0.f;
    if (i < GNUM)       d_gcnt[i] = 0.f;
}

// --------------------------- tiny precomputes ----------------------------------
__global__ void prep_kernel(const float* __restrict__ W_edge, const float* __restrict__ b_edge,
                            const float* __restrict__ W_pre,  const float* __restrict__ b_pre,
                            const float* __restrict__ b_post, const float* __restrict__ W_lin,
                            const float* __restrict__ b_lin) {
    int i = blockIdx.x * blockDim.x + threadIdx.x;
    if (i < 64 * 128) {
        int k = i >> 7, j = i & 127;
        d_Wds[i] = (j < 64) ? W_pre[k * 64 + j] : W_pre[(64 + k) * 64 + (j - 64)];
    } else if (i < 64 * 128 + 128) {
        int j = i - 64 * 128;
        float acc = b_lin[j];
        for (int k = 0; k < 128; k++) acc = fmaf(b_post[k], W_lin[k * 128 + j], acc);
        d_bc[j] = acc;
    } else if (i < 64 * 128 + 128 + 64) {
        int j = i - (64 * 128 + 128);
        float av = 0.f, ac = 0.f;
        for (int k = 0; k < 64; k++) {
            float w = W_pre[(128 + k) * 64 + j];
            av = fmaf(W_edge[k], w, av);
            ac = fmaf(b_edge[k], w, ac);
        }
        d_v[j]    = av;
        d_cvec[j] = ac + b_pre[j];
    }
}

// ---------------- fast fp32x2 GEMM, N fixed at 128, BK=16 ----------------------
// C[M,128] = A_virt[M,K] @ B[K,128] (+bias). K % 16 == 0.
// MODE 0: A plain row-major with leading dim lda (= K).
// MODE 1: virtual A row = [x(64) | agg(256) | agg*amp(256) | agg*iamp(256)], K=832.
template <int MODE>
__global__ __launch_bounds__(256) void sgemm_kernel(
    const float* __restrict__ A, const float* __restrict__ B,
    const float* __restrict__ bias, float* __restrict__ C,
    int M, int K, int lda) {
    __shared__ __align__(16) float As[2][16][132];   // transposed: As[k][m]
    __shared__ __align__(16) float Bs[2][16][128];

    const int tid  = threadIdx.x;
    const int row0 = blockIdx.x * 128;
    const int tr   = (tid >> 4) << 3;
    const int tc   = (tid & 15) << 3;

    unsigned long long acc2[8][4];
#pragma unroll
    for (int i = 0; i < 8; i++)
#pragma unroll
        for (int p = 0; p < 4; p++) acc2[i][p] = 0ull;

    // per-thread load coords (2 A-float4s, 2 B-float4s per k-tile)
    const int am[2] = { (tid + 0) >> 2, (tid + 256) >> 2 };
    const int akq   = tid & 3;                      // same for both (256 % 4 == 0)
    const int bkr[2]= { tid >> 5, (tid + 256) >> 5 };
    const int bnq   = (tid & 31) << 2;

    float4 aS[2], bS[2];

    auto loadT = [&](int k0) {
#pragma unroll
        for (int t = 0; t < 2; t++) {
            int n = row0 + am[t];
            int c = k0 + akq * 4;
            float4 v = make_float4(0.f, 0.f, 0.f, 0.f);
            if (n < M) {
                if (MODE == 0) {
                    v = *reinterpret_cast<const float4*>(A + (size_t)n * lda + c);
                } else {
                    if (c < 64) {
                        v = *reinterpret_cast<const float4*>(A + (size_t)n * 64 + c);
                    } else {
                        int cc = c - 64;
                        int g  = cc >> 8;
                        int o  = cc & 255;
                        v = *reinterpret_cast<const float4*>(d_agg + (size_t)n * 256 + o);
                        if (g != 0) {
                            float s = (g == 1) ? d_amp[n] : d_iamp[n];
                            v.x *= s; v.y *= s; v.z *= s; v.w *= s;
                        }
                    }
                }
            }
            aS[t] = v;
            bS[t] = *reinterpret_cast<const float4*>(B + (size_t)(k0 + bkr[t]) * 128 + bnq);
        }
    };
    auto storeT = [&](int buf) {
#pragma unroll
        for (int t = 0; t < 2; t++) {
            As[buf][akq * 4 + 0][am[t]] = aS[t].x;
            As[buf][akq * 4 + 1][am[t]] = aS[t].y;
            As[buf][akq * 4 + 2][am[t]] = aS[t].z;
            As[buf][akq * 4 + 3][am[t]] = aS[t].w;
            *reinterpret_cast<float4*>(&Bs[buf][bkr[t]][bnq]) = bS[t];
        }
    };

    const int KT = K >> 4;
    loadT(0);
    storeT(0);
    __syncthreads();

    int buf = 0;
    for (int kt = 0; kt < KT; kt++) {
        if (kt + 1 < KT) loadT((kt + 1) << 4);
#pragma unroll
        for (int kk = 0; kk < 16; kk++) {
            float4 a0 = *reinterpret_cast<const float4*>(&As[buf][kk][tr]);
            float4 a1 = *reinterpret_cast<const float4*>(&As[buf][kk][tr + 4]);
            ulonglong2 b0 = *reinterpret_cast<const ulonglong2*>(&Bs[buf][kk][tc]);
            ulonglong2 b1 = *reinterpret_cast<const ulonglong2*>(&Bs[buf][kk][tc + 4]);
            unsigned long long bv[4] = {b0.x, b0.y, b1.x, b1.y};
            float a[8] = {a0.x, a0.y, a0.z, a0.w, a1.x, a1.y, a1.z, a1.w};
#pragma unroll
            for (int i = 0; i < 8; i++) {
                unsigned long long aa = dup2(a[i]);
#pragma unroll
                for (int p = 0; p < 4; p++) acc2[i][p] = fma2(aa, bv[p], acc2[i][p]);
            }
        }
        if (kt + 1 < KT) {
            storeT(buf ^ 1);
            __syncthreads();
            buf ^= 1;
        }
    }

    // epilogue
#pragma unroll
    for (int i = 0; i < 8; i++) {
        int gr = row0 + tr + i;
        if (gr >= M) continue;
        float cv[8];
#pragma unroll
        for (int p = 0; p < 4; p++) unpack2(acc2[i][p], cv[2 * p], cv[2 * p + 1]);
        if (bias) {
#pragma unroll
            for (int q = 0; q < 8; q++) cv[q] += bias[tc + q];
        }
        *reinterpret_cast<float4*>(C + (size_t)gr * 128 + tc) =
            make_float4(cv[0], cv[1], cv[2], cv[3]);
        *reinterpret_cast<float4*>(C + (size_t)gr * 128 + tc + 4) =
            make_float4(cv[4], cv[5], cv[6], cv[7]);
    }
}

// ------------------------------- CSR build -------------------------------------
__global__ void count_kernel(const int* __restrict__ ei, int E) {
    int e = blockIdx.x * blockDim.x + threadIdx.x;
    if (e >= E) return;
    atomicAdd(&d_deg[ei[E + e]], 1);
}

__global__ void scan_kernel(int Nn) {
    __shared__ int sh[1024];
    int t = threadIdx.x;
    int C = (Nn + 1023) >> 10;
    int start = t * C;
    int end = start + C; if (end > Nn) end = Nn;
    int local = 0;
    for (int i = start; i < end; i++) local += d_deg[i];
    sh[t] = local;
    __syncthreads();
    for (int d = 1; d < 1024; d <<= 1) {
        int v = (t >= d) ? sh[t - d] : 0;
        __syncthreads();
        sh[t] += v;
        __syncthreads();
    }
    int run = (t == 0) ? 0 : sh[t - 1];
    for (int i = start; i < end; i++) {
        d_off[i] = run;
        d_fill[i] = run;
        run += d_deg[i];
    }
}

__global__ void scatter_kernel(const int* __restrict__ ei, const float* __restrict__ ea, int E) {
    int e = blockIdx.x * blockDim.x + threadIdx.x;
    if (e >= E) return;
    int d = ei[E + e];
    int pos = atomicAdd(&d_fill[d], 1);
    d_srcS[pos] = ei[e];
    d_eaS[pos]  = ea[e];
}

// -------- per-node aggregation (no atomics) -> compact agg + amp scalars -------
// 256 threads = 4 nodes x 64 feature-threads.
__global__ __launch_bounds__(256) void agg_kernel(int Nn) {
    int tid = threadIdx.x;
    int n = blockIdx.x * 4 + (tid >> 6);
    if (n >= Nn) return;
    int f = tid & 63;

    int off = d_off[n];
    int deg = d_deg[n];
    float pdf = d_pq[n * 128 + f];
    float vf  = d_v[f];
    float cf  = d_cvec[f];

    float sum = 0.f, sq = 0.f;
    float mn = INFINITY, mx = -INFINITY;
#pragma unroll 2
    for (int jj = 0; jj < deg; jj++) {
        int   s   = d_srcS[off + jj];
        float eav = d_eaS[off + jj];
        float m = pdf + d_pq[s * 128 + 64 + f] + eav * vf + cf;
        sum += m;
        sq = fmaf(m, m, sq);
        mn = fminf(mn, m);
        mx = fmaxf(mx, m);
    }

    float ct    = (float)deg;
    float cnt1  = fmaxf(ct, 1.f);
    float inv   = 1.f / cnt1;
    float mean  = sum * inv;
    float mean2 = sq * inv;
    float var   = mean2 - mean * mean;
    float sd    = sqrtf(fmaxf(var, 0.f) + 1e-5f);
    float vmn   = (deg > 0) ? mn : 0.f;
    float vmx   = (deg > 0) ? mx : 0.f;
    float amp   = logf(cnt1 + 1.f) * (1.0f / 2.19722457733621938f);  // / log(9)

    float* Ap = d_agg + (size_t)n * 256;
    Ap[f]       = mean;
    Ap[64 + f]  = vmn;
    Ap[128 + f] = vmx;
    Ap[192 + f] = sd;
    if (f == 0) {
        d_amp[n]  = amp;
        d_iamp[n] = 1.f / amp;
    }
}

// --------------------------------- pooling -------------------------------------
__global__ void pool_kernel(const int* __restrict__ batch, int Nn) {
    int idx = blockIdx.x * blockDim.x + threadIdx.x;
    int n = idx >> 7;
    if (n >= Nn) return;
    int j = idx & 127;
    int g = batch[n];
    atomicAdd(&d_zsum[g * 128 + j], d_h[n * 128 + j]);
    if (j == 0) atomicAdd(&d_gcnt[g], 1.f);
}

// ------------------------------- MLP head --------------------------------------
__device__ __forceinline__ void mlp_stats(float ps, float pq2, int rr, int j,
                                          float* redS, float* redQ,
                                          float* sgS, float* sbS,
                                          const float* __restrict__ g,
                                          const float* __restrict__ be) {
    redS[rr * 128 + j] = ps;
    redQ[rr * 128 + j] = pq2;
    __syncthreads();
    if (rr == 0) {
        float s = 0.f, q = 0.f;
#pragma unroll
        for (int r = 0; r < 8; r++) { s += redS[r * 128 + j]; q += redQ[r * 128 + j]; }
        float mu  = s * (1.f / 64.f);
        float var = q * (1.f / 64.f) - mu * mu;
        float is  = rsqrtf(fmaxf(var, 0.f) + 1e-5f);
        float sg  = g[j] * is;
        sgS[j] = sg;
        sbS[j] = be[j] - mu * sg;
    }
    __syncthreads();
}

__device__ __forceinline__ void mlp_layer(float* zS, float* redS, float* redQ,
                                          float* sgS, float* sbS,
                                          const float* __restrict__ W, const float* __restrict__ b,
                                          const float* __restrict__ g, const float* __restrict__ be,
                                          int rr, int j, float* rsave, const float* radd) {
    float acc[8];
#pragma unroll
    for (int u = 0; u < 8; u++) {
        int i = rr + u * 8;
        float a = b[j];
        for (int k = 0; k < 128; k++) a = fmaf(zS[i * 128 + k], W[k * 128 + j], a);
        acc[u] = a;
    }
    float ps = 0.f, pq2 = 0.f;
#pragma unroll
    for (int u = 0; u < 8; u++) { ps += acc[u]; pq2 = fmaf(acc[u], acc[u], pq2); }
    mlp_stats(ps, pq2, rr, j, redS, redQ, sgS, sbS, g, be);   // syncs cover zS reads
#pragma unroll
    for (int u = 0; u < 8; u++) {
        float val = acc[u] * sgS[j] + sbS[j];
        if (radd) val += radd[u];
        val = fmaxf(val, 0.f);
        zS[(rr + u * 8) * 128 + j] = val;
        if (rsave) rsave[u] = val;
    }
    __syncthreads();
}

__global__ __launch_bounds__(1024) void mlp_kernel(
        const float* __restrict__ g1,  const float* __restrict__ be1,
        const float* __restrict__ W2,  const float* __restrict__ b2,
        const float* __restrict__ g2,  const float* __restrict__ be2,
        const float* __restrict__ Wr1, const float* __restrict__ br1,
        const float* __restrict__ gr1, const float* __restrict__ ber1,
        const float* __restrict__ Wr2, const float* __restrict__ br2,
        const float* __restrict__ gr2, const float* __restrict__ ber2,
        const float* __restrict__ Wout, const float* __restrict__ bout,
        float* __restrict__ out) {
    __shared__ float zS[64 * 128];
    __shared__ float redS[8 * 128];
    __shared__ float redQ[8 * 128];
    __shared__ float sgS[128], sbS[128];
    int tid = threadIdx.x;
    int rr = tid >> 7, j = tid & 127;

    float v8[8];
#pragma unroll
    for (int u = 0; u < 8; u++) {
        int i = rr + u * 8;
        float gc = fmaxf(d_gcnt[i], 1.f);
        v8[u] = d_zsum[i * 128 + j] / gc;
    }
    {
        float ps = 0.f, pq2 = 0.f;
#pragma unroll
        for (int u = 0; u < 8; u++) { ps += v8[u]; pq2 = fmaf(v8[u], v8[u], pq2); }
        mlp_stats(ps, pq2, rr, j, redS, redQ, sgS, sbS, g1, be1);
#pragma unroll
        for (int u = 0; u < 8; u++)
            zS[(rr + u * 8) * 128 + j] = fmaxf(v8[u] * sgS[j] + sbS[j], 0.f);
        __syncthreads();
    }

    float res[8];
    mlp_layer(zS, redS, redQ, sgS, sbS, W2,  b2,  g2,  be2,  rr, j, res,    nullptr);
    mlp_layer(zS, redS, redQ, sgS, sbS, Wr1, br1, gr1, ber1, rr, j, nullptr, nullptr);
    mlp_layer(zS, redS, redQ, sgS, sbS, Wr2, br2, gr2, ber2, rr, j, nullptr, res);

    if (tid < 64) {
        float a = bout[0];
        for (int k = 0; k < 128; k++) a = fmaf(zS[tid * 128 + k], Wout[k], a);
        out[tid] = a;
    }
}

// --------------------------------- launch --------------------------------------
extern "C" void kernel_launch(void* const* d_in, const int* in_sizes, int n_in,
                              void* d_out, int out_size) {
    const float* x      = (const float*)d_in[0];
    const int*   ei     = (const int*)d_in[1];
    const float* ea     = (const float*)d_in[2];
    const int*   batch  = (const int*)d_in[3];
    const float* W_edge = (const float*)d_in[4];
    const float* b_edge = (const float*)d_in[5];
    const float* W_pre  = (const float*)d_in[6];
    const float* b_pre  = (const float*)d_in[7];
    const float* W_post = (const float*)d_in[8];
    const float* b_post = (const float*)d_in[9];
    const float* W_lin  = (const float*)d_in[10];
    const float* b_lin  = (const float*)d_in[11];
    const float* g1  = (const float*)d_in[12];
    const float* be1 = (const float*)d_in[13];
    const float* W2  = (const float*)d_in[14];
    const float* b2  = (const float*)d_in[15];
    const float* g2  = (const float*)d_in[16];
    const float* be2 = (const float*)d_in[17];
    const float* Wr1 = (const float*)d_in[18];
    const float* br1 = (const float*)d_in[19];
    const float* gr1 = (const float*)d_in[20];
    const float* ber1= (const float*)d_in[21];
    const float* Wr2 = (const float*)d_in[22];
    const float* br2 = (const float*)d_in[23];
    const float* gr2 = (const float*)d_in[24];
    const float* ber2= (const float*)d_in[25];
    const float* Wout= (const float*)d_in[26];
    const float* bout= (const float*)d_in[27];
    float* out = (float*)d_out;

    const int Nn = in_sizes[0] / 64;
    const int E  = in_sizes[2];

    void *p_pq, *p_Wds, *p_Wc, *p_bc, *p_h;
    cudaGetSymbolAddress(&p_pq,   d_pq);
    cudaGetSymbolAddress(&p_Wds,  d_Wds);
    cudaGetSymbolAddress(&p_Wc,   d_Wc);
    cudaGetSymbolAddress(&p_bc,   d_bc);
    cudaGetSymbolAddress(&p_h,    d_h);

    init_kernel<<<(Nn + 255) / 256, 256>>>(Nn);
    prep_kernel<<<(64 * 128 + 128 + 64 + 255) / 256, 256>>>(W_edge, b_edge, W_pre, b_pre,
                                                            b_post, W_lin, b_lin);
    // Wc = W_post @ W_lin   [832,128] @ [128,128]
    sgemm_kernel<0><<<(832 + 127) / 128, 256>>>(W_post, W_lin, nullptr, (float*)p_Wc,
                                                832, 128, 128);
    // pq = x @ [Wd|Ws]      [N,64] @ [64,128]
    sgemm_kernel<0><<<(Nn + 127) / 128, 256>>>(x, (const float*)p_Wds, nullptr,
                                               (float*)p_pq, Nn, 64, 64);
    count_kernel<<<(E + 255) / 256, 256>>>(ei, E);
    scan_kernel<<<1, 1024>>>(Nn);
    scatter_kernel<<<(E + 255) / 256, 256>>>(ei, ea, E);
    agg_kernel<<<(Nn + 3) / 4, 256>>>(Nn);
    // h = virt_feat @ Wc + bc   [N,832] @ [832,128], A built on the fly
    sgemm_kernel<1><<<(Nn + 127) / 128, 256>>>(x, (const float*)p_Wc,
                                               (const float*)p_bc, (float*)p_h,
                                               Nn, 832, 0);
    pool_kernel<<<(Nn * 128 + 255) / 256, 256>>>(batch, Nn);
    mlp_kernel<<<1, 1024>>>(g1, be1, W2, b2, g2, be2, Wr1, br1, gr1, ber1,
                            Wr2, br2, gr2, ber2, Wout, bout, out);
}